// round 1
// baseline (speedup 1.0000x reference)
#include <cuda_runtime.h>
#include <math.h>

// ---------------- problem constants ----------------
#define N_NODESC 50000
#define NVC      50001               // + virtual node
#define NEC      400000
#define EDGC     (NEC + 2*N_NODESC + NVC)   // 550001 effective edges
#define IN_DIMC  256
#define HIDC     128
#define HEADSC   2
#define DHIDC    (HEADSC*HIDC)       // 256
#define OUT_DIMC 64

// ---------------- scratch (static device globals; no allocs) ----------------
__device__ float    d_Xv  [NVC * IN_DIMC];   // input with vnode row appended
__device__ float    d_H   [NVC * DHIDC];     // per-layer h (n, head, o)
__device__ float    d_Feat[NVC * HIDC];      // layer output / next input
__device__ float    d_Agg [NVC * HIDC];      // aggregated (mean over heads)
__device__ float    d_As  [NVC * HEADSC];
__device__ float    d_Ad  [NVC * HEADSC];
__device__ unsigned d_Mord[NVC * HEADSC];    // ordered-uint segment max
__device__ float    d_Den [NVC * HEADSC];
__device__ float    d_E   [EDGC * HEADSC];   // edge logits, then exp values
__device__ float    d_vacc[IN_DIMC];

// ---------------- helpers ----------------
__device__ __forceinline__ unsigned fenc(float f) {
    unsigned u = __float_as_uint(f);
    return (u & 0x80000000u) ? ~u : (u | 0x80000000u);
}
__device__ __forceinline__ float fdec(unsigned u) {
    return (u & 0x80000000u) ? __uint_as_float(u ^ 0x80000000u)
                             : __uint_as_float(~u);
}
#define ENC_NEG_INF 0x007FFFFFu   // fenc(-inf)

__device__ __forceinline__ void edge_sd(int e, const int* __restrict__ ei,
                                        int& s, int& d) {
    if (e < NEC)                   { s = ei[e];              d = ei[NEC + e]; }
    else if (e < NEC + N_NODESC)   { s = e - NEC;            d = N_NODESC;    }
    else if (e < NEC + 2*N_NODESC) { s = N_NODESC;           d = e - NEC - N_NODESC; }
    else                           { s = e - NEC - 2*N_NODESC; d = s; }
}

// ---------------- vnode mean ----------------
__global__ void vacc_zero_k() { d_vacc[threadIdx.x] = 0.f; }

__global__ void vnode_partial_k(const float* __restrict__ X) {
    int t = threadIdx.x;
    float loc = 0.f;
    for (int r = blockIdx.x; r < N_NODESC; r += gridDim.x)
        loc += X[r * IN_DIMC + t];
    atomicAdd(&d_vacc[t], loc);
}
__global__ void vnode_fin_k() {
    int t = threadIdx.x;
    d_Xv[N_NODESC * IN_DIMC + t] = d_vacc[t] * (1.f / (float)N_NODESC);
}

// ---------------- dense GEMM: out[r][t] = sum_i x[r][i] * w[i][t] (+bias) ----------------
template<int DIN, int DOUT, int TM>
__global__ void gemm_k(const float* __restrict__ x, const float* __restrict__ w,
                       const float* __restrict__ bias, float* __restrict__ out,
                       int nrows) {
    __shared__ float xs[TM * DIN];
    const int t  = threadIdx.x;         // DOUT threads
    const int r0 = blockIdx.x * TM;
    for (int idx = t; idx < TM * DIN; idx += DOUT) {
        int m = idx / DIN, c = idx % DIN;
        int r = r0 + m;
        xs[idx] = (r < nrows) ? x[r * DIN + c] : 0.f;
    }
    __syncthreads();
    float acc[TM];
#pragma unroll
    for (int m = 0; m < TM; m++) acc[m] = 0.f;
#pragma unroll 4
    for (int i = 0; i < DIN; i++) {
        float wv = w[i * DOUT + t];
#pragma unroll
        for (int m = 0; m < TM; m++) acc[m] += xs[m * DIN + i] * wv;
    }
    float bv = bias ? bias[t] : 0.f;
#pragma unroll
    for (int m = 0; m < TM; m++) {
        int r = r0 + m;
        if (r < nrows) out[r * DOUT + t] = acc[m] + bv;
    }
}

// ---------------- attention logits per node: alpha_s/d = sum_o h*a ----------------
__global__ void alpha_k(const float* __restrict__ asrc,
                        const float* __restrict__ adst) {
    int n = blockIdx.x, t = threadIdx.x;           // 256 threads
    float hv = d_H[n * DHIDC + t];
    __shared__ float ss[DHIDC], sd[DHIDC];
    ss[t] = hv * asrc[t];
    sd[t] = hv * adst[t];
    __syncthreads();
    for (int off = 64; off >= 1; off >>= 1) {
        if ((t & 127) < off) { ss[t] += ss[t + off]; sd[t] += sd[t + off]; }
        __syncthreads();
    }
    if ((t & 127) == 0) {
        int head = t >> 7;
        d_As[n * 2 + head] = ss[t];
        d_Ad[n * 2 + head] = sd[t];
    }
}

// ---------------- per-layer init ----------------
__global__ void init_k() {
    int i = blockIdx.x * blockDim.x + threadIdx.x;
    if (i < NVC * HIDC) d_Agg[i] = 0.f;
    if (i < NVC * HEADSC) { d_Mord[i] = ENC_NEG_INF; d_Den[i] = 0.f; }
}

// ---------------- edge logits + segment max ----------------
__global__ void score_k(const int* __restrict__ ei) {
    int e = blockIdx.x * blockDim.x + threadIdx.x;
    if (e >= EDGC) return;
    int s, d; edge_sd(e, ei, s, d);
#pragma unroll
    for (int h = 0; h < 2; h++) {
        float v = d_As[s * 2 + h] + d_Ad[d * 2 + h];
        v = v > 0.f ? v : 0.2f * v;                 // leaky relu
        d_E[e * 2 + h] = v;
        atomicMax(&d_Mord[d * 2 + h], fenc(v));
    }
}

// ---------------- exp + denominator ----------------
__global__ void exp_k(const int* __restrict__ ei) {
    int e = blockIdx.x * blockDim.x + threadIdx.x;
    if (e >= EDGC) return;
    int s, d; edge_sd(e, ei, s, d);
#pragma unroll
    for (int h = 0; h < 2; h++) {
        float m  = fdec(d_Mord[d * 2 + h]);
        float ex = expf(d_E[e * 2 + h] - m);
        d_E[e * 2 + h] = ex;
        atomicAdd(&d_Den[d * 2 + h], ex);
    }
}

// ---------------- weighted aggregate: warp per edge ----------------
__global__ void agg_k(const int* __restrict__ ei) {
    int gid  = blockIdx.x * blockDim.x + threadIdx.x;
    int e    = gid >> 5;
    int lane = gid & 31;
    if (e >= EDGC) return;
    int s, d; edge_sd(e, ei, s, d);
    float a0 = d_E[e * 2]     / (d_Den[d * 2]     + 1e-16f) * 0.5f;
    float a1 = d_E[e * 2 + 1] / (d_Den[d * 2 + 1] + 1e-16f) * 0.5f;
    float4 v0 = *(const float4*)&d_H[s * DHIDC +        lane * 4];
    float4 v1 = *(const float4*)&d_H[s * DHIDC + HIDC + lane * 4];
    float* o = &d_Agg[d * HIDC + lane * 4];
    atomicAdd(o + 0, a0 * v0.x + a1 * v1.x);
    atomicAdd(o + 1, a0 * v0.y + a1 * v1.y);
    atomicAdd(o + 2, a0 * v0.z + a1 * v1.z);
    atomicAdd(o + 3, a0 * v0.w + a1 * v1.w);
}

// ---------------- bias + layernorm + exact gelu ----------------
__global__ void ln_k(const float* __restrict__ b, const float* __restrict__ g,
                     const float* __restrict__ be) {
    int n = blockIdx.x, t = threadIdx.x;  // 128 threads
    float v = d_Agg[n * HIDC + t] + b[t];
    __shared__ float sh[HIDC];
    sh[t] = v; __syncthreads();
    for (int off = 64; off >= 1; off >>= 1) {
        if (t < off) sh[t] += sh[t + off];
        __syncthreads();
    }
    float mu = sh[0] * (1.f / HIDC);
    __syncthreads();
    float dv = v - mu;
    sh[t] = dv * dv; __syncthreads();
    for (int off = 64; off >= 1; off >>= 1) {
        if (t < off) sh[t] += sh[t + off];
        __syncthreads();
    }
    float var = sh[0] * (1.f / HIDC);
    float y  = dv * rsqrtf(var + 1e-5f) * g[t] + be[t];
    float ge = 0.5f * y * (1.f + erff(y * 0.70710678118654752f));
    d_Feat[n * HIDC + t] = ge;
}

// ---------------- host launch ----------------
extern "C" void kernel_launch(void* const* d_in, const int* in_sizes, int n_in,
                              void* d_out, int out_size) {
    (void)in_sizes; (void)n_in; (void)out_size;
    const float* X  = (const float*)d_in[0];
    const int*   ei = (const int*)  d_in[1];
    // d_in[2] = edge_weight (unused by reference)
    const float* W[3]   = {(const float*)d_in[3],  (const float*)d_in[9],  (const float*)d_in[15]};
    const float* aS[3]  = {(const float*)d_in[4],  (const float*)d_in[10], (const float*)d_in[16]};
    const float* aD[3]  = {(const float*)d_in[5],  (const float*)d_in[11], (const float*)d_in[17]};
    const float* bb[3]  = {(const float*)d_in[6],  (const float*)d_in[12], (const float*)d_in[18]};
    const float* gg[3]  = {(const float*)d_in[7],  (const float*)d_in[13], (const float*)d_in[19]};
    const float* bE[3]  = {(const float*)d_in[8],  (const float*)d_in[14], (const float*)d_in[20]};
    const float* Wout   = (const float*)d_in[21];
    const float* bout   = (const float*)d_in[22];
    float* out = (float*)d_out;

    // vnode mean + assemble Xv
    cudaMemcpyToSymbolAsync(d_Xv, X, (size_t)N_NODESC * IN_DIMC * sizeof(float),
                            0, cudaMemcpyDeviceToDevice, 0);
    vacc_zero_k<<<1, IN_DIMC>>>();
    vnode_partial_k<<<512, IN_DIMC>>>(X);
    vnode_fin_k<<<1, IN_DIMC>>>();

    const int gemm_blocks = (NVC + 15) / 16;
    const int edge_blocks = (EDGC + 255) / 256;
    const int agg_blocks  = (EDGC * 32 + 255) / 256;
    const int init_blocks = (NVC * HIDC + 255) / 256;
    float* dH;    cudaGetSymbolAddress((void**)&dH,    d_H);
    float* dXv;   cudaGetSymbolAddress((void**)&dXv,   d_Xv);
    float* dFeat; cudaGetSymbolAddress((void**)&dFeat, d_Feat);

    for (int l = 0; l < 3; l++) {
        if (l == 0)
            gemm_k<IN_DIMC, DHIDC, 16><<<gemm_blocks, DHIDC>>>(dXv, W[0], nullptr, dH, NVC);
        else
            gemm_k<HIDC, DHIDC, 16><<<gemm_blocks, DHIDC>>>(dFeat, W[l], nullptr, dH, NVC);
        alpha_k<<<NVC, DHIDC>>>(aS[l], aD[l]);
        init_k<<<init_blocks, 256>>>();
        score_k<<<edge_blocks, 256>>>(ei);
        exp_k<<<edge_blocks, 256>>>(ei);
        agg_k<<<agg_blocks, 256>>>(ei);
        ln_k<<<NVC, HIDC>>>(bb[l], gg[l], bE[l]);
    }

    // final projection (only real nodes)
    gemm_k<HIDC, OUT_DIMC, 16><<<(N_NODESC + 15) / 16, OUT_DIMC>>>(
        dFeat, Wout, bout, out, N_NODESC);
}

// round 2
// speedup vs baseline: 4.7293x; 4.7293x over previous
#include <cuda_runtime.h>
#include <math.h>

// ---------------- problem constants ----------------
#define N_NODESC 50000
#define NVC      50001
#define VN       N_NODESC
#define NEC      400000
#define IN_DIMC  256
#define HIDC     128
#define DHIDC    256
#define OUT_DIMC 64
#define NB_SCAN  98            // ceil(50000/512)
#define VROWS    391           // ceil(NVC/128)

// ---------------- scratch ----------------
__device__ __align__(16) float d_Xv  [NVC * IN_DIMC];
__device__ __align__(16) float d_H   [NVC * DHIDC];
__device__ __align__(16) float d_Feat[NVC * HIDC];
__device__ float d_As[NVC * 2];
__device__ float d_Ad[NVC * 2];
__device__ int   d_cnt   [N_NODESC];
__device__ int   d_rowptr[N_NODESC + 1];
__device__ int   d_cursor[N_NODESC];
__device__ int   d_csr   [NEC];
__device__ int   d_bsumex[NB_SCAN + 1];
__device__ float d_vacc[IN_DIMC];
__device__ unsigned d_vmax[2];
__device__ float d_vden[2];
__device__ float d_vagg[DHIDC];

// ---------------- helpers ----------------
__device__ __forceinline__ unsigned fenc(float f) {
    unsigned u = __float_as_uint(f);
    return (u & 0x80000000u) ? ~u : (u | 0x80000000u);
}
__device__ __forceinline__ float fdec(unsigned u) {
    return (u & 0x80000000u) ? __uint_as_float(u ^ 0x80000000u)
                             : __uint_as_float(~u);
}
#define ENC_NEG_INF 0x007FFFFFu

__device__ __forceinline__ float lrelu(float v) { return v > 0.f ? v : 0.2f * v; }
__device__ __forceinline__ float wsum(float v) {
#pragma unroll
    for (int o = 16; o; o >>= 1) v += __shfl_xor_sync(0xffffffffu, v, o);
    return v;
}
__device__ __forceinline__ float wmax(float v) {
#pragma unroll
    for (int o = 16; o; o >>= 1) v = fmaxf(v, __shfl_xor_sync(0xffffffffu, v, o));
    return v;
}

// ---------------- vnode input mean ----------------
__global__ void vacc_zero_k() { d_vacc[threadIdx.x] = 0.f; }
__global__ void vnode_partial_k(const float* __restrict__ X) {
    int t = threadIdx.x;
    float loc = 0.f;
    for (int r = blockIdx.x; r < N_NODESC; r += gridDim.x)
        loc += X[r * IN_DIMC + t];
    atomicAdd(&d_vacc[t], loc);
}
__global__ void vnode_fin_k() {
    int t = threadIdx.x;
    d_Xv[N_NODESC * IN_DIMC + t] = d_vacc[t] * (1.f / (float)N_NODESC);
}

// ---------------- CSR build ----------------
__global__ void hist_k(const int* __restrict__ ei) {
    int e = blockIdx.x * blockDim.x + threadIdx.x;
    if (e < NEC) atomicAdd(&d_cnt[ei[NEC + e]], 1);
}
__global__ void scanb_k() {     // 1 block: block-sums + exclusive scan of them
    // each of 98 "virtual blocks" covers 512 counts; thread computes one blocksum
    __shared__ int bs[NB_SCAN];
    int b = threadIdx.x;
    if (b < NB_SCAN) {
        int s = 0;
        int base = b * 512;
#pragma unroll 8
        for (int i = 0; i < 512; i++) {
            int idx = base + i;
            if (idx < N_NODESC) s += d_cnt[idx];
        }
        bs[b] = s;
    }
    __syncthreads();
    if (threadIdx.x == 0) {
        int carry = 0;
        for (int i = 0; i < NB_SCAN; i++) { d_bsumex[i] = carry; carry += bs[i]; }
        d_bsumex[NB_SCAN] = carry;
    }
}
__global__ void rowptr_k() {    // NB_SCAN blocks x 512: in-block exclusive scan
    __shared__ int sh[512];
    int t = threadIdx.x;
    int idx = blockIdx.x * 512 + t;
    int c = (idx < N_NODESC) ? d_cnt[idx] : 0;
    sh[t] = c;
    __syncthreads();
#pragma unroll
    for (int o = 1; o < 512; o <<= 1) {
        int v = (t >= o) ? sh[t - o] : 0;
        __syncthreads();
        sh[t] += v;
        __syncthreads();
    }
    if (idx < N_NODESC) {
        int p = d_bsumex[blockIdx.x] + sh[t] - c;
        d_rowptr[idx] = p;
        d_cursor[idx] = p;
    }
    if (idx == 0) d_rowptr[N_NODESC] = NEC;
}
__global__ void scatter_k(const int* __restrict__ ei) {
    int e = blockIdx.x * blockDim.x + threadIdx.x;
    if (e >= NEC) return;
    int d = ei[NEC + e];
    int p = atomicAdd(&d_cursor[d], 1);
    d_csr[p] = ei[e];
}

// ---------------- dense GEMM (float4 inner) ----------------
template<int DIN, int DOUT, int TM>
__global__ void gemm_k(const float* __restrict__ x, const float* __restrict__ w,
                       const float* __restrict__ bias, float* __restrict__ out,
                       int nrows) {
    __shared__ __align__(16) float xs[TM * DIN];
    const int t  = threadIdx.x;       // DOUT threads
    const int r0 = blockIdx.x * TM;
    const float4 z4 = make_float4(0.f, 0.f, 0.f, 0.f);
    for (int idx = t; idx < TM * DIN / 4; idx += DOUT) {
        int m = idx / (DIN / 4), c = idx % (DIN / 4);
        int r = r0 + m;
        ((float4*)xs)[idx] = (r < nrows) ? ((const float4*)x)[(size_t)r * (DIN / 4) + c] : z4;
    }
    __syncthreads();
    float acc[TM];
#pragma unroll
    for (int m = 0; m < TM; m++) acc[m] = 0.f;
    for (int i = 0; i < DIN; i += 4) {
        float w0 = w[(i + 0) * DOUT + t];
        float w1 = w[(i + 1) * DOUT + t];
        float w2 = w[(i + 2) * DOUT + t];
        float w3 = w[(i + 3) * DOUT + t];
#pragma unroll
        for (int m = 0; m < TM; m++) {
            float4 x4 = *(const float4*)&xs[m * DIN + i];
            acc[m] = fmaf(x4.x, w0, fmaf(x4.y, w1, fmaf(x4.z, w2, fmaf(x4.w, w3, acc[m]))));
        }
    }
    float bv = bias ? bias[t] : 0.f;
#pragma unroll
    for (int m = 0; m < TM; m++) {
        int r = r0 + m;
        if (r < nrows) out[(size_t)r * DOUT + t] = acc[m] + bv;
    }
}

// ---------------- attention logits per node ----------------
__global__ void alpha_k(const float* __restrict__ asrc,
                        const float* __restrict__ adst) {
    int n = blockIdx.x, t = threadIdx.x;           // 256 threads
    float hv = d_H[n * DHIDC + t];
    __shared__ float ss[DHIDC], sd[DHIDC];
    ss[t] = hv * asrc[t];
    sd[t] = hv * adst[t];
    __syncthreads();
    for (int off = 64; off >= 1; off >>= 1) {
        if ((t & 127) < off) { ss[t] += ss[t + off]; sd[t] += sd[t + off]; }
        __syncthreads();
    }
    if ((t & 127) == 0) {
        int head = t >> 7;
        d_As[n * 2 + head] = ss[t];
        d_Ad[n * 2 + head] = sd[t];
    }
}

// ---------------- vnode destination (50001 in-edges) ----------------
__global__ void vn_init_k() {
    int t = threadIdx.x;
    d_vagg[t] = 0.f;
    if (t < 2) { d_vmax[t] = ENC_NEG_INF; d_vden[t] = 0.f; }
}
__global__ void vn_max_k() {
    int idx = blockIdx.x * 512 + threadIdx.x;
    float Ad0 = d_Ad[2 * VN], Ad1 = d_Ad[2 * VN + 1];
    float m0 = -INFINITY, m1 = -INFINITY;
    if (idx < NVC) {
        m0 = lrelu(d_As[2 * idx] + Ad0);
        m1 = lrelu(d_As[2 * idx + 1] + Ad1);
    }
    __shared__ float s0[512], s1[512];
    int t = threadIdx.x;
    s0[t] = m0; s1[t] = m1;
    __syncthreads();
    for (int o = 256; o; o >>= 1) {
        if (t < o) { s0[t] = fmaxf(s0[t], s0[t + o]); s1[t] = fmaxf(s1[t], s1[t + o]); }
        __syncthreads();
    }
    if (t == 0) { atomicMax(&d_vmax[0], fenc(s0[0])); atomicMax(&d_vmax[1], fenc(s1[0])); }
}
__global__ void vn_den_k() {
    int idx = blockIdx.x * 512 + threadIdx.x;
    float Ad0 = d_Ad[2 * VN], Ad1 = d_Ad[2 * VN + 1];
    float m0 = fdec(d_vmax[0]), m1 = fdec(d_vmax[1]);
    float e0 = 0.f, e1 = 0.f;
    if (idx < NVC) {
        e0 = expf(lrelu(d_As[2 * idx] + Ad0) - m0);
        e1 = expf(lrelu(d_As[2 * idx + 1] + Ad1) - m1);
    }
    __shared__ float s0[512], s1[512];
    int t = threadIdx.x;
    s0[t] = e0; s1[t] = e1;
    __syncthreads();
    for (int o = 256; o; o >>= 1) {
        if (t < o) { s0[t] += s0[t + o]; s1[t] += s1[t + o]; }
        __syncthreads();
    }
    if (t == 0) { atomicAdd(&d_vden[0], s0[0]); atomicAdd(&d_vden[1], s1[0]); }
}
__global__ void vn_agg_k() {   // 128 blocks x 256 threads
    int t = threadIdx.x;
    int r0 = blockIdx.x * VROWS;
    int r1 = min(r0 + VROWS, NVC);
    float Ad0 = d_Ad[2 * VN], Ad1 = d_Ad[2 * VN + 1];
    float m0 = fdec(d_vmax[0]), m1 = fdec(d_vmax[1]);
    __shared__ float w0sh[256], w1sh[256];
    float acc = 0.f;
    int head = t >> 7;
    for (int base = r0; base < r1; base += 256) {
        int r = base + t;
        if (r < r1) {
            w0sh[t] = expf(lrelu(d_As[2 * r] + Ad0) - m0);
            w1sh[t] = expf(lrelu(d_As[2 * r + 1] + Ad1) - m1);
        }
        __syncthreads();
        int cnt = min(256, r1 - base);
        const float* wsh = head ? w1sh : w0sh;
        for (int j = 0; j < cnt; j++)
            acc += wsh[j] * d_H[(size_t)(base + j) * DHIDC + t];
        __syncthreads();
    }
    atomicAdd(&d_vagg[t], acc);
}
__global__ void vn_fin_k(const float* __restrict__ b, const float* __restrict__ g,
                         const float* __restrict__ be) {
    int t = threadIdx.x;   // 128
    float den0 = d_vden[0] + 1e-16f, den1 = d_vden[1] + 1e-16f;
    float v = 0.5f * (d_vagg[t] / den0 + d_vagg[HIDC + t] / den1) + b[t];
    __shared__ float sh[HIDC];
    sh[t] = v; __syncthreads();
    for (int o = 64; o; o >>= 1) { if (t < o) sh[t] += sh[t + o]; __syncthreads(); }
    float mu = sh[0] * (1.f / HIDC);
    __syncthreads();
    float dv = v - mu;
    sh[t] = dv * dv; __syncthreads();
    for (int o = 64; o; o >>= 1) { if (t < o) sh[t] += sh[t + o]; __syncthreads(); }
    float var = sh[0] * (1.f / HIDC);
    float y = dv * rsqrtf(var + 1e-5f) * g[t] + be[t];
    d_Feat[(size_t)VN * HIDC + t] = 0.5f * y * (1.f + erff(y * 0.70710678118654752f));
}

// ---------------- fused per-node: softmax + aggregate + bias + LN + GELU ----------------
__global__ void node_k(const float* __restrict__ b, const float* __restrict__ g,
                       const float* __restrict__ be) {
    int gid  = blockIdx.x * blockDim.x + threadIdx.x;
    int d    = gid >> 5;
    int lane = gid & 31;
    if (d >= N_NODESC) return;
    float Ad0 = d_Ad[2 * d], Ad1 = d_Ad[2 * d + 1];
    int off = d_rowptr[d], end = d_rowptr[d + 1];

    float ev0 = lrelu(d_As[2 * VN] + Ad0), ev1 = lrelu(d_As[2 * VN + 1] + Ad1);
    float es0 = lrelu(d_As[2 * d]  + Ad0), es1 = lrelu(d_As[2 * d + 1]  + Ad1);

    float m0 = fmaxf(ev0, es0), m1 = fmaxf(ev1, es1);
    for (int i = off + lane; i < end; i += 32) {
        int s = d_csr[i];
        m0 = fmaxf(m0, lrelu(d_As[2 * s]     + Ad0));
        m1 = fmaxf(m1, lrelu(d_As[2 * s + 1] + Ad1));
    }
    m0 = wmax(m0); m1 = wmax(m1);

    float den0 = 0.f, den1 = 0.f;
    for (int i = off + lane; i < end; i += 32) {
        int s = d_csr[i];
        den0 += expf(lrelu(d_As[2 * s]     + Ad0) - m0);
        den1 += expf(lrelu(d_As[2 * s + 1] + Ad1) - m1);
    }
    den0 = wsum(den0) + expf(ev0 - m0) + expf(es0 - m0);
    den1 = wsum(den1) + expf(ev1 - m1) + expf(es1 - m1);
    float inv0 = 0.5f / (den0 + 1e-16f);
    float inv1 = 0.5f / (den1 + 1e-16f);

    float ax = 0.f, ay = 0.f, az = 0.f, aw = 0.f;
    const int c = lane * 4;
    for (int j = off; j < end; j++) {
        int s = d_csr[j];
        float w0 = expf(lrelu(d_As[2 * s]     + Ad0) - m0) * inv0;
        float w1 = expf(lrelu(d_As[2 * s + 1] + Ad1) - m1) * inv1;
        float4 v0 = *(const float4*)&d_H[(size_t)s * DHIDC + c];
        float4 v1 = *(const float4*)&d_H[(size_t)s * DHIDC + HIDC + c];
        ax += w0 * v0.x + w1 * v1.x;
        ay += w0 * v0.y + w1 * v1.y;
        az += w0 * v0.z + w1 * v1.z;
        aw += w0 * v0.w + w1 * v1.w;
    }
    {   // vnode in-edge
        float w0 = expf(ev0 - m0) * inv0, w1 = expf(ev1 - m1) * inv1;
        float4 v0 = *(const float4*)&d_H[(size_t)VN * DHIDC + c];
        float4 v1 = *(const float4*)&d_H[(size_t)VN * DHIDC + HIDC + c];
        ax += w0 * v0.x + w1 * v1.x; ay += w0 * v0.y + w1 * v1.y;
        az += w0 * v0.z + w1 * v1.z; aw += w0 * v0.w + w1 * v1.w;
    }
    {   // self loop
        float w0 = expf(es0 - m0) * inv0, w1 = expf(es1 - m1) * inv1;
        float4 v0 = *(const float4*)&d_H[(size_t)d * DHIDC + c];
        float4 v1 = *(const float4*)&d_H[(size_t)d * DHIDC + HIDC + c];
        ax += w0 * v0.x + w1 * v1.x; ay += w0 * v0.y + w1 * v1.y;
        az += w0 * v0.z + w1 * v1.z; aw += w0 * v0.w + w1 * v1.w;
    }

    // bias + LN + GELU over the 128 values owned by this warp
    float y0 = ax + b[c], y1 = ay + b[c + 1], y2 = az + b[c + 2], y3 = aw + b[c + 3];
    float mu = wsum(y0 + y1 + y2 + y3) * (1.f / HIDC);
    float d0 = y0 - mu, d1 = y1 - mu, d2 = y2 - mu, d3 = y3 - mu;
    float var = wsum(d0 * d0 + d1 * d1 + d2 * d2 + d3 * d3) * (1.f / HIDC);
    float rs = rsqrtf(var + 1e-5f);
    float z0 = d0 * rs * g[c]     + be[c];
    float z1 = d1 * rs * g[c + 1] + be[c + 1];
    float z2 = d2 * rs * g[c + 2] + be[c + 2];
    float z3 = d3 * rs * g[c + 3] + be[c + 3];
    const float k = 0.70710678118654752f;
    float4 o;
    o.x = 0.5f * z0 * (1.f + erff(z0 * k));
    o.y = 0.5f * z1 * (1.f + erff(z1 * k));
    o.z = 0.5f * z2 * (1.f + erff(z2 * k));
    o.w = 0.5f * z3 * (1.f + erff(z3 * k));
    *(float4*)&d_Feat[(size_t)d * HIDC + c] = o;
}

// ---------------- host launch ----------------
extern "C" void kernel_launch(void* const* d_in, const int* in_sizes, int n_in,
                              void* d_out, int out_size) {
    (void)in_sizes; (void)n_in; (void)out_size;
    const float* X  = (const float*)d_in[0];
    const int*   ei = (const int*)  d_in[1];
    const float* W[3]  = {(const float*)d_in[3],  (const float*)d_in[9],  (const float*)d_in[15]};
    const float* aS[3] = {(const float*)d_in[4],  (const float*)d_in[10], (const float*)d_in[16]};
    const float* aD[3] = {(const float*)d_in[5],  (const float*)d_in[11], (const float*)d_in[17]};
    const float* bb[3] = {(const float*)d_in[6],  (const float*)d_in[12], (const float*)d_in[18]};
    const float* gg[3] = {(const float*)d_in[7],  (const float*)d_in[13], (const float*)d_in[19]};
    const float* bE[3] = {(const float*)d_in[8],  (const float*)d_in[14], (const float*)d_in[20]};
    const float* Wout  = (const float*)d_in[21];
    const float* bout  = (const float*)d_in[22];
    float* out = (float*)d_out;

    float *dH, *dXv, *dFeat;
    cudaGetSymbolAddress((void**)&dH, d_H);
    cudaGetSymbolAddress((void**)&dXv, d_Xv);
    cudaGetSymbolAddress((void**)&dFeat, d_Feat);
    int* dCnt; cudaGetSymbolAddress((void**)&dCnt, d_cnt);

    // vnode-augmented input
    cudaMemcpyToSymbolAsync(d_Xv, X, (size_t)N_NODESC * IN_DIMC * sizeof(float),
                            0, cudaMemcpyDeviceToDevice, 0);
    vacc_zero_k<<<1, IN_DIMC>>>();
    vnode_partial_k<<<512, IN_DIMC>>>(X);
    vnode_fin_k<<<1, IN_DIMC>>>();

    // CSR over dst (original edges only; vnode/self edges are implicit)
    cudaMemsetAsync(dCnt, 0, N_NODESC * sizeof(int), 0);
    const int eb = (NEC + 255) / 256;
    hist_k<<<eb, 256>>>(ei);
    scanb_k<<<1, 128>>>();
    rowptr_k<<<NB_SCAN, 512>>>();
    scatter_k<<<eb, 256>>>(ei);

    const int gemm_blocks = (NVC + 15) / 16;
    const int node_blocks = (N_NODESC * 32 + 255) / 256;

    for (int l = 0; l < 3; l++) {
        if (l == 0)
            gemm_k<IN_DIMC, DHIDC, 16><<<gemm_blocks, DHIDC>>>(dXv, W[0], nullptr, dH, NVC);
        else
            gemm_k<HIDC, DHIDC, 16><<<gemm_blocks, DHIDC>>>(dFeat, W[l], nullptr, dH, NVC);
        alpha_k<<<NVC, DHIDC>>>(aS[l], aD[l]);
        vn_init_k<<<1, DHIDC>>>();
        vn_max_k<<<NB_SCAN, 512>>>();
        vn_den_k<<<NB_SCAN, 512>>>();
        vn_agg_k<<<128, 256>>>();
        vn_fin_k<<<1, HIDC>>>(bb[l], gg[l], bE[l]);
        node_k<<<node_blocks, 256>>>(bb[l], gg[l], bE[l]);
    }

    gemm_k<HIDC, OUT_DIMC, 16><<<(N_NODESC + 15) / 16, OUT_DIMC>>>(
        dFeat, Wout, bout, out, N_NODESC);
}

// round 3
// speedup vs baseline: 5.7809x; 1.2224x over previous
#include <cuda_runtime.h>
#include <math.h>

// ---------------- problem constants ----------------
#define N_NODESC 50000
#define NVC      50001
#define VN       N_NODESC
#define NEC      400000
#define IN_DIMC  256
#define HIDC     128
#define DHIDC    256
#define OUT_DIMC 64
#define NB_SCAN  98
#define VROWS    391

// ---------------- scratch ----------------
__device__ __align__(16) float d_Xv  [NVC * IN_DIMC];
__device__ __align__(16) float d_H   [NVC * DHIDC];
__device__ __align__(16) float d_Feat[NVC * HIDC];
__device__ float d_As[NVC * 2];
__device__ float d_Ad[NVC * 2];
__device__ int   d_cnt   [N_NODESC];
__device__ int   d_rowptr[N_NODESC + 1];
__device__ int   d_cursor[N_NODESC];
__device__ int   d_csr   [NEC];
__device__ int   d_bsumex[NB_SCAN + 1];
__device__ float d_vacc[IN_DIMC];
__device__ unsigned d_vmax[2];
__device__ float d_vden[2];
__device__ float d_vagg[DHIDC];

// ---------------- helpers ----------------
__device__ __forceinline__ unsigned fenc(float f) {
    unsigned u = __float_as_uint(f);
    return (u & 0x80000000u) ? ~u : (u | 0x80000000u);
}
__device__ __forceinline__ float fdec(unsigned u) {
    return (u & 0x80000000u) ? __uint_as_float(u ^ 0x80000000u)
                             : __uint_as_float(~u);
}
#define ENC_NEG_INF 0x007FFFFFu

__device__ __forceinline__ float lrelu(float v) { return v > 0.f ? v : 0.2f * v; }
__device__ __forceinline__ float wsum(float v) {
#pragma unroll
    for (int o = 16; o; o >>= 1) v += __shfl_xor_sync(0xffffffffu, v, o);
    return v;
}
__device__ __forceinline__ float wmax(float v) {
#pragma unroll
    for (int o = 16; o; o >>= 1) v = fmaxf(v, __shfl_xor_sync(0xffffffffu, v, o));
    return v;
}
__device__ __forceinline__ void ffma2(unsigned long long& d, unsigned long long a,
                                      unsigned long long b) {
    asm("fma.rn.f32x2 %0, %1, %2, %0;" : "+l"(d) : "l"(a), "l"(b));
}
__device__ __forceinline__ float lo32(unsigned long long v) {
    return __uint_as_float((unsigned)v);
}
__device__ __forceinline__ float hi32(unsigned long long v) {
    return __uint_as_float((unsigned)(v >> 32));
}

// ---------------- vnode input mean ----------------
__global__ void vacc_zero_k() { d_vacc[threadIdx.x] = 0.f; }
__global__ void vnode_partial_k(const float* __restrict__ X) {
    int t = threadIdx.x;
    float loc = 0.f;
    for (int r = blockIdx.x; r < N_NODESC; r += gridDim.x)
        loc += X[r * IN_DIMC + t];
    atomicAdd(&d_vacc[t], loc);
}
__global__ void vnode_fin_k() {
    int t = threadIdx.x;
    d_Xv[N_NODESC * IN_DIMC + t] = d_vacc[t] * (1.f / (float)N_NODESC);
}

// ---------------- CSR build ----------------
__global__ void hist_k(const int* __restrict__ ei) {
    int e = blockIdx.x * blockDim.x + threadIdx.x;
    if (e < NEC) atomicAdd(&d_cnt[ei[NEC + e]], 1);
}
__global__ void scanb_k() {
    __shared__ int bs[NB_SCAN];
    int b = threadIdx.x;
    if (b < NB_SCAN) {
        int s = 0;
        int base = b * 512;
#pragma unroll 8
        for (int i = 0; i < 512; i++) {
            int idx = base + i;
            if (idx < N_NODESC) s += d_cnt[idx];
        }
        bs[b] = s;
    }
    __syncthreads();
    if (threadIdx.x == 0) {
        int carry = 0;
        for (int i = 0; i < NB_SCAN; i++) { d_bsumex[i] = carry; carry += bs[i]; }
        d_bsumex[NB_SCAN] = carry;
    }
}
__global__ void rowptr_k() {
    __shared__ int sh[512];
    int t = threadIdx.x;
    int idx = blockIdx.x * 512 + t;
    int c = (idx < N_NODESC) ? d_cnt[idx] : 0;
    sh[t] = c;
    __syncthreads();
#pragma unroll
    for (int o = 1; o < 512; o <<= 1) {
        int v = (t >= o) ? sh[t - o] : 0;
        __syncthreads();
        sh[t] += v;
        __syncthreads();
    }
    if (idx < N_NODESC) {
        int p = d_bsumex[blockIdx.x] + sh[t] - c;
        d_rowptr[idx] = p;
        d_cursor[idx] = p;
    }
    if (idx == 0) d_rowptr[N_NODESC] = NEC;
}
__global__ void scatter_k(const int* __restrict__ ei) {
    int e = blockIdx.x * blockDim.x + threadIdx.x;
    if (e >= NEC) return;
    int d = ei[NEC + e];
    int p = atomicAdd(&d_cursor[d], 1);
    d_csr[p] = ei[e];
}

// ---------------- f32x2 register-blocked GEMM ----------------
// BM=128, BN in {128,64}; 8x8 microtile; optional fused alpha epilogue.
template<int BN>
__global__ void sgemm_k(const float* __restrict__ A, const float* __restrict__ B,
                        const float* __restrict__ bias, float* __restrict__ C,
                        int M, int K, int N,
                        const float* __restrict__ aS, const float* __restrict__ aD) {
    constexpr int BM  = 128;
    constexpr int BK  = 16;
    constexpr int TPB = 2 * BN;          // 256 or 128 threads
    constexpr int GRP = BN / 8;          // tn groups: 16 or 8

    __shared__ __align__(16) float2 As2[BK][BM];   // duplicated pairs
    __shared__ __align__(16) float  Bs [BK][BN];

    const int tid = threadIdx.x;
    const int tn  = tid % GRP;
    const int tm  = tid / GRP;           // 0..15
    const int row0 = blockIdx.y * BM;
    const int col0 = blockIdx.x * BN;

    unsigned long long acc[8][4];
#pragma unroll
    for (int i = 0; i < 8; i++)
#pragma unroll
        for (int j = 0; j < 4; j++) acc[i][j] = 0ull;

    for (int k0 = 0; k0 < K; k0 += BK) {
        __syncthreads();
        // load A tile (BM x BK) -> duplicated-pair transposed
#pragma unroll
        for (int s = tid; s < BM * 4; s += TPB) {
            int r = s >> 2, q = s & 3;
            int row = row0 + r;
            float4 v = (row < M) ? *(const float4*)&A[(size_t)row * K + k0 + q * 4]
                                 : make_float4(0.f, 0.f, 0.f, 0.f);
            As2[q * 4 + 0][r] = make_float2(v.x, v.x);
            As2[q * 4 + 1][r] = make_float2(v.y, v.y);
            As2[q * 4 + 2][r] = make_float2(v.z, v.z);
            As2[q * 4 + 3][r] = make_float2(v.w, v.w);
        }
        // load B tile (BK x BN)
#pragma unroll
        for (int s = tid; s < BK * BN / 4; s += TPB) {
            int br = s / (BN / 4), bc = s % (BN / 4);
            *(float4*)&Bs[br][bc * 4] =
                *(const float4*)&B[(size_t)(k0 + br) * N + col0 + bc * 4];
        }
        __syncthreads();

#pragma unroll
        for (int kk = 0; kk < BK; kk++) {
            unsigned long long a[8], b[4];
            const ulonglong2* ap = (const ulonglong2*)&As2[kk][tm * 8];
            ulonglong2 a01 = ap[0], a23 = ap[1], a45 = ap[2], a67 = ap[3];
            a[0] = a01.x; a[1] = a01.y; a[2] = a23.x; a[3] = a23.y;
            a[4] = a45.x; a[5] = a45.y; a[6] = a67.x; a[7] = a67.y;
            const ulonglong2* bp = (const ulonglong2*)&Bs[kk][tn * 8];
            ulonglong2 b01 = bp[0], b23 = bp[1];
            b[0] = b01.x; b[1] = b01.y; b[2] = b23.x; b[3] = b23.y;
#pragma unroll
            for (int i = 0; i < 8; i++)
#pragma unroll
                for (int j = 0; j < 4; j++) ffma2(acc[i][j], a[i], b[j]);
        }
    }

    // epilogue: store C (+bias)
    float bv[8];
#pragma unroll
    for (int j = 0; j < 8; j++) bv[j] = bias ? bias[col0 + tn * 8 + j] : 0.f;
#pragma unroll
    for (int i = 0; i < 8; i++) {
        int row = row0 + tm * 8 + i;
        if (row < M) {
            float4 o0, o1;
            o0.x = lo32(acc[i][0]) + bv[0]; o0.y = hi32(acc[i][0]) + bv[1];
            o0.z = lo32(acc[i][1]) + bv[2]; o0.w = hi32(acc[i][1]) + bv[3];
            o1.x = lo32(acc[i][2]) + bv[4]; o1.y = hi32(acc[i][2]) + bv[5];
            o1.z = lo32(acc[i][3]) + bv[6]; o1.w = hi32(acc[i][3]) + bv[7];
            *(float4*)&C[(size_t)row * N + col0 + tn * 8]     = o0;
            *(float4*)&C[(size_t)row * N + col0 + tn * 8 + 4] = o1;
        }
    }

    // fused alpha: this block covers exactly one head when BN==128
    if (aS) {
        float av[8], dv[8];
#pragma unroll
        for (int j = 0; j < 8; j++) {
            av[j] = aS[col0 + tn * 8 + j];
            dv[j] = aD[col0 + tn * 8 + j];
        }
        int head = (col0 >= HIDC) ? 1 : 0;
#pragma unroll
        for (int i = 0; i < 8; i++) {
            float sa = 0.f, sd = 0.f;
#pragma unroll
            for (int j = 0; j < 4; j++) {
                float l = lo32(acc[i][j]), h = hi32(acc[i][j]);
                sa += l * av[2 * j] + h * av[2 * j + 1];
                sd += l * dv[2 * j] + h * dv[2 * j + 1];
            }
#pragma unroll
            for (int o = GRP / 2; o; o >>= 1) {
                sa += __shfl_xor_sync(0xffffffffu, sa, o);
                sd += __shfl_xor_sync(0xffffffffu, sd, o);
            }
            int row = row0 + tm * 8 + i;
            if (tn == 0 && row < M) {
                d_As[2 * row + head] = sa;
                d_Ad[2 * row + head] = sd;
            }
        }
    }
}

// ---------------- vnode destination (50001 in-edges) ----------------
__global__ void vn_init_k() {
    int t = threadIdx.x;
    d_vagg[t] = 0.f;
    if (t < 2) { d_vmax[t] = ENC_NEG_INF; d_vden[t] = 0.f; }
}
__global__ void vn_max_k() {
    int idx = blockIdx.x * 512 + threadIdx.x;
    float Ad0 = d_Ad[2 * VN], Ad1 = d_Ad[2 * VN + 1];
    float m0 = -INFINITY, m1 = -INFINITY;
    if (idx < NVC) {
        m0 = lrelu(d_As[2 * idx] + Ad0);
        m1 = lrelu(d_As[2 * idx + 1] + Ad1);
    }
    __shared__ float s0[512], s1[512];
    int t = threadIdx.x;
    s0[t] = m0; s1[t] = m1;
    __syncthreads();
    for (int o = 256; o; o >>= 1) {
        if (t < o) { s0[t] = fmaxf(s0[t], s0[t + o]); s1[t] = fmaxf(s1[t], s1[t + o]); }
        __syncthreads();
    }
    if (t == 0) { atomicMax(&d_vmax[0], fenc(s0[0])); atomicMax(&d_vmax[1], fenc(s1[0])); }
}
__global__ void vn_den_k() {
    int idx = blockIdx.x * 512 + threadIdx.x;
    float Ad0 = d_Ad[2 * VN], Ad1 = d_Ad[2 * VN + 1];
    float m0 = fdec(d_vmax[0]), m1 = fdec(d_vmax[1]);
    float e0 = 0.f, e1 = 0.f;
    if (idx < NVC) {
        e0 = expf(lrelu(d_As[2 * idx] + Ad0) - m0);
        e1 = expf(lrelu(d_As[2 * idx + 1] + Ad1) - m1);
    }
    __shared__ float s0[512], s1[512];
    int t = threadIdx.x;
    s0[t] = e0; s1[t] = e1;
    __syncthreads();
    for (int o = 256; o; o >>= 1) {
        if (t < o) { s0[t] += s0[t + o]; s1[t] += s1[t + o]; }
        __syncthreads();
    }
    if (t == 0) { atomicAdd(&d_vden[0], s0[0]); atomicAdd(&d_vden[1], s1[0]); }
}
__global__ void vn_agg_k() {
    int t = threadIdx.x;
    int r0 = blockIdx.x * VROWS;
    int r1 = min(r0 + VROWS, NVC);
    float Ad0 = d_Ad[2 * VN], Ad1 = d_Ad[2 * VN + 1];
    float m0 = fdec(d_vmax[0]), m1 = fdec(d_vmax[1]);
    __shared__ float w0sh[256], w1sh[256];
    float acc = 0.f;
    int head = t >> 7;
    for (int base = r0; base < r1; base += 256) {
        int r = base + t;
        if (r < r1) {
            w0sh[t] = expf(lrelu(d_As[2 * r] + Ad0) - m0);
            w1sh[t] = expf(lrelu(d_As[2 * r + 1] + Ad1) - m1);
        }
        __syncthreads();
        int cnt = min(256, r1 - base);
        const float* wsh = head ? w1sh : w0sh;
        for (int j = 0; j < cnt; j++)
            acc += wsh[j] * d_H[(size_t)(base + j) * DHIDC + t];
        __syncthreads();
    }
    atomicAdd(&d_vagg[t], acc);
}
__global__ void vn_fin_k(const float* __restrict__ b, const float* __restrict__ g,
                         const float* __restrict__ be) {
    int t = threadIdx.x;
    float den0 = d_vden[0] + 1e-16f, den1 = d_vden[1] + 1e-16f;
    float v = 0.5f * (d_vagg[t] / den0 + d_vagg[HIDC + t] / den1) + b[t];
    __shared__ float sh[HIDC];
    sh[t] = v; __syncthreads();
    for (int o = 64; o; o >>= 1) { if (t < o) sh[t] += sh[t + o]; __syncthreads(); }
    float mu = sh[0] * (1.f / HIDC);
    __syncthreads();
    float dv = v - mu;
    sh[t] = dv * dv; __syncthreads();
    for (int o = 64; o; o >>= 1) { if (t < o) sh[t] += sh[t + o]; __syncthreads(); }
    float var = sh[0] * (1.f / HIDC);
    float y = dv * rsqrtf(var + 1e-5f) * g[t] + be[t];
    d_Feat[(size_t)VN * HIDC + t] = 0.5f * y * (1.f + erff(y * 0.70710678118654752f));
}

// ---------------- fused per-node softmax+aggregate+bias+LN+GELU ----------------
__global__ void node_k(const float* __restrict__ b, const float* __restrict__ g,
                       const float* __restrict__ be) {
    int gid  = blockIdx.x * blockDim.x + threadIdx.x;
    int d    = gid >> 5;
    int lane = gid & 31;
    if (d >= N_NODESC) return;
    float Ad0 = d_Ad[2 * d], Ad1 = d_Ad[2 * d + 1];
    int off = d_rowptr[d], end = d_rowptr[d + 1];

    float ev0 = lrelu(d_As[2 * VN] + Ad0), ev1 = lrelu(d_As[2 * VN + 1] + Ad1);
    float es0 = lrelu(d_As[2 * d]  + Ad0), es1 = lrelu(d_As[2 * d + 1]  + Ad1);

    float m0 = fmaxf(ev0, es0), m1 = fmaxf(ev1, es1);
    for (int i = off + lane; i < end; i += 32) {
        int s = d_csr[i];
        m0 = fmaxf(m0, lrelu(d_As[2 * s]     + Ad0));
        m1 = fmaxf(m1, lrelu(d_As[2 * s + 1] + Ad1));
    }
    m0 = wmax(m0); m1 = wmax(m1);

    float den0 = 0.f, den1 = 0.f;
    for (int i = off + lane; i < end; i += 32) {
        int s = d_csr[i];
        den0 += expf(lrelu(d_As[2 * s]     + Ad0) - m0);
        den1 += expf(lrelu(d_As[2 * s + 1] + Ad1) - m1);
    }
    den0 = wsum(den0) + expf(ev0 - m0) + expf(es0 - m0);
    den1 = wsum(den1) + expf(ev1 - m1) + expf(es1 - m1);
    float inv0 = 0.5f / (den0 + 1e-16f);
    float inv1 = 0.5f / (den1 + 1e-16f);

    float ax = 0.f, ay = 0.f, az = 0.f, aw = 0.f;
    const int c = lane * 4;
    for (int j = off; j < end; j++) {
        int s = d_csr[j];
        float w0 = expf(lrelu(d_As[2 * s]     + Ad0) - m0) * inv0;
        float w1 = expf(lrelu(d_As[2 * s + 1] + Ad1) - m1) * inv1;
        float4 v0 = *(const float4*)&d_H[(size_t)s * DHIDC + c];
        float4 v1 = *(const float4*)&d_H[(size_t)s * DHIDC + HIDC + c];
        ax += w0 * v0.x + w1 * v1.x;
        ay += w0 * v0.y + w1 * v1.y;
        az += w0 * v0.z + w1 * v1.z;
        aw += w0 * v0.w + w1 * v1.w;
    }
    {
        float w0 = expf(ev0 - m0) * inv0, w1 = expf(ev1 - m1) * inv1;
        float4 v0 = *(const float4*)&d_H[(size_t)VN * DHIDC + c];
        float4 v1 = *(const float4*)&d_H[(size_t)VN * DHIDC + HIDC + c];
        ax += w0 * v0.x + w1 * v1.x; ay += w0 * v0.y + w1 * v1.y;
        az += w0 * v0.z + w1 * v1.z; aw += w0 * v0.w + w1 * v1.w;
    }
    {
        float w0 = expf(es0 - m0) * inv0, w1 = expf(es1 - m1) * inv1;
        float4 v0 = *(const float4*)&d_H[(size_t)d * DHIDC + c];
        float4 v1 = *(const float4*)&d_H[(size_t)d * DHIDC + HIDC + c];
        ax += w0 * v0.x + w1 * v1.x; ay += w0 * v0.y + w1 * v1.y;
        az += w0 * v0.z + w1 * v1.z; aw += w0 * v0.w + w1 * v1.w;
    }

    float y0 = ax + b[c], y1 = ay + b[c + 1], y2 = az + b[c + 2], y3 = aw + b[c + 3];
    float mu = wsum(y0 + y1 + y2 + y3) * (1.f / HIDC);
    float d0 = y0 - mu, d1 = y1 - mu, d2 = y2 - mu, d3 = y3 - mu;
    float var = wsum(d0 * d0 + d1 * d1 + d2 * d2 + d3 * d3) * (1.f / HIDC);
    float rs = rsqrtf(var + 1e-5f);
    float z0 = d0 * rs * g[c]     + be[c];
    float z1 = d1 * rs * g[c + 1] + be[c + 1];
    float z2 = d2 * rs * g[c + 2] + be[c + 2];
    float z3 = d3 * rs * g[c + 3] + be[c + 3];
    const float kk = 0.70710678118654752f;
    float4 o;
    o.x = 0.5f * z0 * (1.f + erff(z0 * kk));
    o.y = 0.5f * z1 * (1.f + erff(z1 * kk));
    o.z = 0.5f * z2 * (1.f + erff(z2 * kk));
    o.w = 0.5f * z3 * (1.f + erff(z3 * kk));
    *(float4*)&d_Feat[(size_t)d * HIDC + c] = o;
}

// ---------------- host launch ----------------
extern "C" void kernel_launch(void* const* d_in, const int* in_sizes, int n_in,
                              void* d_out, int out_size) {
    (void)in_sizes; (void)n_in; (void)out_size;
    const float* X  = (const float*)d_in[0];
    const int*   ei = (const int*)  d_in[1];
    const float* W[3]  = {(const float*)d_in[3],  (const float*)d_in[9],  (const float*)d_in[15]};
    const float* aS[3] = {(const float*)d_in[4],  (const float*)d_in[10], (const float*)d_in[16]};
    const float* aD[3] = {(const float*)d_in[5],  (const float*)d_in[11], (const float*)d_in[17]};
    const float* bb[3] = {(const float*)d_in[6],  (const float*)d_in[12], (const float*)d_in[18]};
    const float* gg[3] = {(const float*)d_in[7],  (const float*)d_in[13], (const float*)d_in[19]};
    const float* bE[3] = {(const float*)d_in[8],  (const float*)d_in[14], (const float*)d_in[20]};
    const float* Wout  = (const float*)d_in[21];
    const float* bout  = (const float*)d_in[22];
    float* out = (float*)d_out;

    float *dH, *dXv, *dFeat;
    cudaGetSymbolAddress((void**)&dH, d_H);
    cudaGetSymbolAddress((void**)&dXv, d_Xv);
    cudaGetSymbolAddress((void**)&dFeat, d_Feat);
    int* dCnt; cudaGetSymbolAddress((void**)&dCnt, d_cnt);

    cudaMemcpyToSymbolAsync(d_Xv, X, (size_t)N_NODESC * IN_DIMC * sizeof(float),
                            0, cudaMemcpyDeviceToDevice, 0);
    vacc_zero_k<<<1, IN_DIMC>>>();
    vnode_partial_k<<<512, IN_DIMC>>>(X);
    vnode_fin_k<<<1, IN_DIMC>>>();

    cudaMemsetAsync(dCnt, 0, N_NODESC * sizeof(int), 0);
    const int eb = (NEC + 255) / 256;
    hist_k<<<eb, 256>>>(ei);
    scanb_k<<<1, 128>>>();
    rowptr_k<<<NB_SCAN, 512>>>();
    scatter_k<<<eb, 256>>>(ei);

    const int mrows = (NVC + 127) / 128;        // 391
    const int node_blocks = (N_NODESC * 32 + 255) / 256;

    for (int l = 0; l < 3; l++) {
        dim3 grid(DHIDC / 128, mrows);
        if (l == 0)
            sgemm_k<128><<<grid, 256>>>(dXv, W[0], nullptr, dH, NVC, IN_DIMC, DHIDC,
                                        aS[l], aD[l]);
        else
            sgemm_k<128><<<grid, 256>>>(dFeat, W[l], nullptr, dH, NVC, HIDC, DHIDC,
                                        aS[l], aD[l]);
        vn_init_k<<<1, DHIDC>>>();
        vn_max_k<<<NB_SCAN, 512>>>();
        vn_den_k<<<NB_SCAN, 512>>>();
        vn_agg_k<<<128, 256>>>();
        vn_fin_k<<<1, HIDC>>>(bb[l], gg[l], bE[l]);
        node_k<<<node_blocks, 256>>>(bb[l], gg[l], bE[l]);
    }

    dim3 gridF(1, (N_NODESC + 127) / 128);
    sgemm_k<64><<<gridF, 128>>>(dFeat, Wout, bout, out, N_NODESC, HIDC, OUT_DIMC,
                                nullptr, nullptr);
}